// round 8
// baseline (speedup 1.0000x reference)
#include <cuda_runtime.h>
#include <cuda_bf16.h>
#include <cstdint>

// Problem constants (fixed by the dataset)
#define NN 50000
#define EE 1600000
#define HD 128
#define FDMAX 256

// -------- device scratch (no allocations allowed) --------
__device__ __nv_bfloat16 g_fb0[(size_t)NN * FDMAX];  // bf16 node features
__device__ __nv_bfloat16 g_b1[(size_t)NN * HD];      // bf16 feature buffers
__device__ __nv_bfloat16 g_b2[(size_t)NN * HD];
__device__ __nv_bfloat16 g_b3[(size_t)NN * HD];
__device__ __nv_bfloat16 g_wt[FDMAX * HD + 6 * HD * HD];  // transposed bf16 weights
__device__ float g_dis[NN];
__device__ int   g_cnt[NN];       // in-degree (no self loop)
__device__ int   g_rowstart[NN];  // CSR row start (by dst)
__device__ int   g_woff[NN];      // running write offsets for fill
__device__ int   g_bsum[256];     // block sums for scan
__device__ int   g_boff[256];     // exclusive block offsets
__device__ int2  g_sd[EE];        // (src, dst) per original edge
__device__ int2  g_epack[EE];     // CSR payload: (src, coef bits)
__device__ int   g_is64;

// weight offsets inside g_wt (bf16 elements)
#define WO_ENC1 0                       // [HD][K1]
#define WO_ENC2 (FDMAX * HD)            // [HD][HD]
#define WO_CONV(l) (WO_ENC2 + (1 + (l)) * HD * HD)
#define WO_CLST (WO_ENC2 + 4 * HD * HD)
#define WO_CLSB (WO_ENC2 + 5 * HD * HD)

// ---------------------------------------------------------
// prep: detect edge dtype (int64 vs int32)
// ---------------------------------------------------------
__global__ void detect_kernel(const int* __restrict__ ei32) {
    if (blockIdx.x == 0 && threadIdx.x == 0) {
        int orv = 0;
        #pragma unroll
        for (int i = 0; i < 16; i++) orv |= ei32[2 * i + 1];
        g_is64 = (orv == 0) ? 1 : 0;   // int64 high words are 0 (values < 50000)
    }
}

__global__ void zero_cnt_kernel(int n) {
    int i = blockIdx.x * blockDim.x + threadIdx.x;
    if (i < n) g_cnt[i] = 0;
}

__global__ void prep_edges_kernel(const void* __restrict__ eiv, int E) {
    int e = blockIdx.x * blockDim.x + threadIdx.x;
    if (e >= E) return;
    int s, d;
    if (g_is64) {
        const long long* ei = (const long long*)eiv;
        s = (int)ei[e];
        d = (int)ei[(size_t)E + e];
    } else {
        const int* ei = (const int*)eiv;
        s = ei[e];
        d = ei[E + e];
    }
    g_sd[e] = make_int2(s, d);
    atomicAdd(&g_cnt[d], 1);
}

__global__ void dis_kernel(int n) {
    int i = blockIdx.x * blockDim.x + threadIdx.x;
    if (i < n) g_dis[i] = rsqrtf((float)g_cnt[i] + 1.0f);  // +1 self-loop
}

// -------- 2-level exclusive scan of g_cnt -> g_rowstart, g_woff --------
__global__ void scan1_kernel(int n) {
    __shared__ int sh[256];
    int tx = threadIdx.x;
    int i  = blockIdx.x * 256 + tx;
    int v  = (i < n) ? g_cnt[i] : 0;
    sh[tx] = v;
    __syncthreads();
    #pragma unroll
    for (int o = 1; o < 256; o <<= 1) {
        int t = (tx >= o) ? sh[tx - o] : 0;
        __syncthreads();
        sh[tx] += t;
        __syncthreads();
    }
    if (i < n) g_rowstart[i] = sh[tx];
    if (tx == 255) g_bsum[blockIdx.x] = sh[255];
}

__global__ void scan2_kernel(int nb) {
    __shared__ int sh[256];
    int tx = threadIdx.x;
    int v  = (tx < nb) ? g_bsum[tx] : 0;
    sh[tx] = v;
    __syncthreads();
    #pragma unroll
    for (int o = 1; o < 256; o <<= 1) {
        int t = (tx >= o) ? sh[tx - o] : 0;
        __syncthreads();
        sh[tx] += t;
        __syncthreads();
    }
    if (tx < nb) g_boff[tx] = sh[tx] - v;
}

__global__ void scan3_kernel(int n) {
    int i = blockIdx.x * blockDim.x + threadIdx.x;
    if (i < n) {
        int start = g_rowstart[i] + g_boff[blockIdx.x] - g_cnt[i];
        g_rowstart[i] = start;
        g_woff[i]     = start;
    }
}

__global__ void fill_kernel(int E) {
    int e = blockIdx.x * blockDim.x + threadIdx.x;
    if (e >= E) return;
    int2 sd = g_sd[e];
    int pos = atomicAdd(&g_woff[sd.y], 1);
    float coef = g_dis[sd.x] * g_dis[sd.y];
    g_epack[pos] = make_int2(sd.x, __float_as_int(coef));
}

// ---------------------------------------------------------
// one-time conversions: weights -> transposed bf16 [n][k], node feats -> bf16
// ---------------------------------------------------------
__global__ void prep_weights_kernel(const float* __restrict__ ew1,
                                    const float* __restrict__ ew2,
                                    const float* __restrict__ cw1,
                                    const float* __restrict__ cw2,
                                    const float* __restrict__ cw3,
                                    const float* __restrict__ clw1, int K1)
{
    int idx = blockIdx.x * blockDim.x + threadIdx.x;
    int enc1_sz = K1 * HD;
    if (idx < enc1_sz) {
        int n = idx / K1, k = idx % K1;
        g_wt[WO_ENC1 + idx] = __float2bfloat16(ew1[k * HD + n]);
        return;
    }
    int r = idx - enc1_sz;
    int seg = r / (HD * HD);
    if (seg >= 6) return;
    int rr = r % (HD * HD);
    int n = rr / HD, k = rr % HD;
    const float* w;
    switch (seg) {
        case 0: w = ew2; break;
        case 1: w = cw1; break;
        case 2: w = cw2; break;
        case 3: w = cw3; break;
        case 4: w = clw1; break;
        default: w = clw1 + HD * HD; break;
    }
    g_wt[enc1_sz + seg * HD * HD + n * HD + k] = __float2bfloat16(w[k * HD + n]);
}

__global__ void cvt_nf_kernel(const float* __restrict__ nf, int total_pairs) {
    int i = blockIdx.x * blockDim.x + threadIdx.x;
    if (i < total_pairs) {
        float2 v = ((const float2*)nf)[i];
        ((__nv_bfloat162*)g_fb0)[i] = __floats2bfloat162_rn(v.x, v.y);
    }
}

// ---------------------------------------------------------
// BF16 tensor-core GEMM: C[M,128] = A[M,K](bf16) @ Wt[128,K]^T + bias [,relu]
// BM=128, BN=128, BK=32, 256 threads (8 warps, 4x2), warp tile 32x64
// mma.sync.aligned.m16n8k16.row.col.f32.bf16.bf16.f32 ; bf16 output
// ---------------------------------------------------------
__device__ __forceinline__ void mma_bf16(float c[4],
                                         uint32_t a0, uint32_t a1, uint32_t a2, uint32_t a3,
                                         uint32_t b0, uint32_t b1) {
    asm volatile(
        "mma.sync.aligned.m16n8k16.row.col.f32.bf16.bf16.f32 "
        "{%0,%1,%2,%3}, {%4,%5,%6,%7}, {%8,%9}, {%0,%1,%2,%3};"
        : "+f"(c[0]), "+f"(c[1]), "+f"(c[2]), "+f"(c[3])
        : "r"(a0), "r"(a1), "r"(a2), "r"(a3), "r"(b0), "r"(b1));
}

#define TS 40   // smem row stride in bf16 (32 + 8 pad) -> conflict-free frag loads

template <bool RELU_OUT>
__global__ __launch_bounds__(256, 2) void bgemm_kernel(
    const __nv_bfloat16* __restrict__ A, const __nv_bfloat16* __restrict__ Bt,
    const float* __restrict__ bias, __nv_bfloat16* __restrict__ C, int M, int K)
{
    __shared__ __align__(16) __nv_bfloat16 As[128 * TS];  // [m][k]
    __shared__ __align__(16) __nv_bfloat16 Bs[128 * TS];  // [n][k]

    const int tid    = threadIdx.x;
    const int wid    = tid >> 5;
    const int lane   = tid & 31;
    const int gid    = lane >> 2;
    const int tig    = lane & 3;
    const int warp_m = wid >> 1;
    const int warp_n = wid & 1;
    const int m0     = blockIdx.x * 128;

    float acc[2][8][4];
    #pragma unroll
    for (int mt = 0; mt < 2; mt++)
        #pragma unroll
        for (int nt = 0; nt < 8; nt++)
            #pragma unroll
            for (int i = 0; i < 4; i++) acc[mt][nt][i] = 0.0f;

    for (int k0 = 0; k0 < K; k0 += 32) {
        // A tile: 128 rows x 32 k bf16 (64B/row) -> 512 uint4, 2 per thread
        #pragma unroll
        for (int i = 0; i < 2; i++) {
            int fi  = tid + i * 256;
            int row = fi >> 2, c = fi & 3;
            uint4 v = make_uint4(0u, 0u, 0u, 0u);
            if (m0 + row < M)
                v = __ldg((const uint4*)(A + (size_t)(m0 + row) * K + k0) + c);
            *(uint4*)&As[row * TS + c * 8] = v;
        }
        // B tile: 128 n x 32 k bf16 from transposed weights
        #pragma unroll
        for (int i = 0; i < 2; i++) {
            int fi = tid + i * 256;
            int n  = fi >> 2, c = fi & 3;
            uint4 v = __ldg((const uint4*)(Bt + (size_t)n * K + k0) + c);
            *(uint4*)&Bs[n * TS + c * 8] = v;
        }
        __syncthreads();

        #pragma unroll
        for (int kk = 0; kk < 32; kk += 16) {
            uint32_t af[2][4];
            #pragma unroll
            for (int mt = 0; mt < 2; mt++) {
                int rbase = warp_m * 32 + mt * 16;
                const __nv_bfloat16* p0 = &As[(rbase + gid)     * TS + kk + tig * 2];
                const __nv_bfloat16* p1 = &As[(rbase + gid + 8) * TS + kk + tig * 2];
                af[mt][0] = *(const uint32_t*)p0;
                af[mt][1] = *(const uint32_t*)p1;
                af[mt][2] = *(const uint32_t*)(p0 + 8);
                af[mt][3] = *(const uint32_t*)(p1 + 8);
            }
            uint32_t bfr[8][2];
            #pragma unroll
            for (int nt = 0; nt < 8; nt++) {
                int n = warp_n * 64 + nt * 8 + gid;
                const __nv_bfloat16* pn = &Bs[n * TS + kk + tig * 2];
                bfr[nt][0] = *(const uint32_t*)pn;
                bfr[nt][1] = *(const uint32_t*)(pn + 8);
            }
            #pragma unroll
            for (int mt = 0; mt < 2; mt++)
                #pragma unroll
                for (int nt = 0; nt < 8; nt++)
                    mma_bf16(acc[mt][nt], af[mt][0], af[mt][1], af[mt][2], af[mt][3],
                             bfr[nt][0], bfr[nt][1]);
        }
        __syncthreads();
    }

    // epilogue: bias + optional relu, bf16x2 stores
    #pragma unroll
    for (int mt = 0; mt < 2; mt++) {
        #pragma unroll
        for (int half = 0; half < 2; half++) {
            int m = m0 + warp_m * 32 + mt * 16 + gid + half * 8;
            if (m < M) {
                #pragma unroll
                for (int nt = 0; nt < 8; nt++) {
                    int col = warp_n * 64 + nt * 8 + tig * 2;
                    float v0 = acc[mt][nt][half * 2 + 0];
                    float v1 = acc[mt][nt][half * 2 + 1];
                    if (bias) {
                        v0 += __ldg(&bias[col]);
                        v1 += __ldg(&bias[col + 1]);
                    }
                    if (RELU_OUT) { v0 = fmaxf(v0, 0.f); v1 = fmaxf(v1, 0.f); }
                    *(__nv_bfloat162*)(C + (size_t)m * HD + col) =
                        __floats2bfloat162_rn(v0, v1);
                }
            }
        }
    }
}

// ---------------------------------------------------------
// helpers: unpack 8 bf16 (uint4) -> 8 floats
// ---------------------------------------------------------
__device__ __forceinline__ void bf8_to_f(uint4 u, float* f) {
    __nv_bfloat162* p = (__nv_bfloat162*)&u;
    float2 a = __bfloat1622float2(p[0]);
    float2 b = __bfloat1622float2(p[1]);
    float2 c = __bfloat1622float2(p[2]);
    float2 d = __bfloat1622float2(p[3]);
    f[0] = a.x; f[1] = a.y; f[2] = b.x; f[3] = b.y;
    f[4] = c.x; f[5] = c.y; f[6] = d.x; f[7] = d.y;
}

// ---------------------------------------------------------
// CSR aggregation: warp per dst node, half-warps take even/odd neighbors,
// 16B gathers, fp32 accumulate, bf16 output.
// out[i] = [relu]( bias + dis[i]^2 * xw[i] + sum_j coef_j * xw[src_j] )
// ---------------------------------------------------------
template <bool RELU>
__global__ void agg_kernel(const __nv_bfloat16* __restrict__ xw,
                           const float* __restrict__ bias,
                           __nv_bfloat16* __restrict__ out, int n)
{
    int g    = blockIdx.x * blockDim.x + threadIdx.x;
    int node = g >> 5;
    int lane = g & 31;
    if (node >= n) return;
    int hl   = lane & 15;   // 16B chunk index: features 8*hl .. 8*hl+7
    int half = lane >> 4;

    int start = g_rowstart[node];
    int deg   = g_cnt[node];

    float acc[8];
    if (half == 0) {
        float ds = g_dis[node];
        float c  = ds * ds;
        float4 b0 = ((const float4*)bias)[hl * 2];
        float4 b1 = ((const float4*)bias)[hl * 2 + 1];
        uint4 u = __ldg((const uint4*)(xw + (size_t)node * HD) + hl);
        float f[8]; bf8_to_f(u, f);
        acc[0] = fmaf(f[0], c, b0.x); acc[1] = fmaf(f[1], c, b0.y);
        acc[2] = fmaf(f[2], c, b0.z); acc[3] = fmaf(f[3], c, b0.w);
        acc[4] = fmaf(f[4], c, b1.x); acc[5] = fmaf(f[5], c, b1.y);
        acc[6] = fmaf(f[6], c, b1.z); acc[7] = fmaf(f[7], c, b1.w);
    } else {
        #pragma unroll
        for (int i = 0; i < 8; i++) acc[i] = 0.0f;
    }

    const int2* ep = g_epack + start;
    int j = 0;
    for (; j + 2 <= deg; j += 2) {
        int2 e = __ldg(ep + j + half);
        float w = __int_as_float(e.y);
        uint4 u = __ldg((const uint4*)(xw + (size_t)e.x * HD) + hl);
        float f[8]; bf8_to_f(u, f);
        #pragma unroll
        for (int i = 0; i < 8; i++) acc[i] = fmaf(f[i], w, acc[i]);
    }
    if ((deg & 1) && half == 0) {
        int2 e = __ldg(ep + deg - 1);
        float w = __int_as_float(e.y);
        uint4 u = __ldg((const uint4*)(xw + (size_t)e.x * HD) + hl);
        float f[8]; bf8_to_f(u, f);
        #pragma unroll
        for (int i = 0; i < 8; i++) acc[i] = fmaf(f[i], w, acc[i]);
    }

    // combine halves
    #pragma unroll
    for (int i = 0; i < 8; i++) acc[i] += __shfl_xor_sync(0xffffffffu, acc[i], 16);

    if (half == 0) {
        if (RELU) {
            #pragma unroll
            for (int i = 0; i < 8; i++) acc[i] = fmaxf(acc[i], 0.f);
        }
        __nv_bfloat162 h0 = __floats2bfloat162_rn(acc[0], acc[1]);
        __nv_bfloat162 h1 = __floats2bfloat162_rn(acc[2], acc[3]);
        __nv_bfloat162 h2 = __floats2bfloat162_rn(acc[4], acc[5]);
        __nv_bfloat162 h3 = __floats2bfloat162_rn(acc[6], acc[7]);
        uint4 u;
        u.x = *(uint32_t*)&h0; u.y = *(uint32_t*)&h1;
        u.z = *(uint32_t*)&h2; u.w = *(uint32_t*)&h3;
        ((uint4*)(out + (size_t)node * HD))[hl] = u;
    }
}

// ---------------------------------------------------------
// edge score: sigmoid( relu(A[s]+B[d]) . w2 + b2 )
// warp per edge (grid-stride): half-warp loads A, half loads B (16B each),
// shfl-exchange, duplicated partials, 4-step reduce. w2/b2 hoisted.
// ---------------------------------------------------------
__global__ void edge_score_kernel(const __nv_bfloat16* __restrict__ Af,
                                  const __nv_bfloat16* __restrict__ Bf,
                                  const float* __restrict__ w2,
                                  const float* __restrict__ b2,
                                  float* __restrict__ out, int E)
{
    int g    = blockIdx.x * blockDim.x + threadIdx.x;
    int warp = g >> 5;
    int lane = g & 31;
    int hl   = lane & 15;
    int half = lane >> 4;
    int nwarps = (gridDim.x * blockDim.x) >> 5;

    float4 w0 = ((const float4*)w2)[hl * 2];
    float4 w1 = ((const float4*)w2)[hl * 2 + 1];
    float bb  = __ldg(b2);

    for (int e = warp; e < E; e += nwarps) {
        int2 sd = __ldg(&g_sd[e]);
        uint4 mine = (half == 0)
            ? __ldg((const uint4*)(Af + (size_t)sd.x * HD) + hl)
            : __ldg((const uint4*)(Bf + (size_t)sd.y * HD) + hl);
        uint4 oth;
        oth.x = __shfl_xor_sync(0xffffffffu, mine.x, 16);
        oth.y = __shfl_xor_sync(0xffffffffu, mine.y, 16);
        oth.z = __shfl_xor_sync(0xffffffffu, mine.z, 16);
        oth.w = __shfl_xor_sync(0xffffffffu, mine.w, 16);

        float fa[8], fb[8];
        if (half == 0) { bf8_to_f(mine, fa); bf8_to_f(oth, fb); }
        else           { bf8_to_f(oth, fa);  bf8_to_f(mine, fb); }

        float s;
        s  = fmaxf(fa[0] + fb[0], 0.f) * w0.x;
        s += fmaxf(fa[1] + fb[1], 0.f) * w0.y;
        s += fmaxf(fa[2] + fb[2], 0.f) * w0.z;
        s += fmaxf(fa[3] + fb[3], 0.f) * w0.w;
        s += fmaxf(fa[4] + fb[4], 0.f) * w1.x;
        s += fmaxf(fa[5] + fb[5], 0.f) * w1.y;
        s += fmaxf(fa[6] + fb[6], 0.f) * w1.z;
        s += fmaxf(fa[7] + fb[7], 0.f) * w1.w;

        #pragma unroll
        for (int o = 8; o; o >>= 1) s += __shfl_xor_sync(0xffffffffu, s, o);
        if (lane == 0)
            out[e] = 1.0f / (1.0f + __expf(-(s + bb)));
    }
}

// ---------------------------------------------------------
// host side
// ---------------------------------------------------------
static void gemm(const __nv_bfloat16* A, const __nv_bfloat16* Bt, const float* bias,
                 __nv_bfloat16* C, int M, int K, bool relu_out)
{
    dim3 grid((M + 127) / 128);
    if (relu_out) bgemm_kernel<true ><<<grid, 256>>>(A, Bt, bias, C, M, K);
    else          bgemm_kernel<false><<<grid, 256>>>(A, Bt, bias, C, M, K);
}

extern "C" void kernel_launch(void* const* d_in, const int* in_sizes, int n_in,
                              void* d_out, int out_size)
{
    const float* nf      = (const float*)d_in[0];
    const void*  ei      = d_in[1];
    const float* enc_w1  = (const float*)d_in[2];
    const float* enc_b1  = (const float*)d_in[3];
    const float* enc_w2  = (const float*)d_in[4];
    const float* enc_b2  = (const float*)d_in[5];
    const float* conv_w[3] = {(const float*)d_in[6], (const float*)d_in[8], (const float*)d_in[10]};
    const float* conv_b[3] = {(const float*)d_in[7], (const float*)d_in[9], (const float*)d_in[11]};
    const float* cls_w1  = (const float*)d_in[12];
    const float* cls_b1  = (const float*)d_in[13];
    const float* cls_w2  = (const float*)d_in[14];
    const float* cls_b2  = (const float*)d_in[15];

    int K1 = in_sizes[2] / HD;        // encoder input dim (256)
    int N  = in_sizes[0] / K1;        // nodes
    int E  = in_sizes[1] / 2;         // edges

    __nv_bfloat16 *pfb0, *pb1, *pb2, *pb3, *pwt;
    cudaGetSymbolAddress((void**)&pfb0, g_fb0);
    cudaGetSymbolAddress((void**)&pb1,  g_b1);
    cudaGetSymbolAddress((void**)&pb2,  g_b2);
    cudaGetSymbolAddress((void**)&pb3,  g_b3);
    cudaGetSymbolAddress((void**)&pwt,  g_wt);

    int nblk = (N + 255) / 256;
    int eblk = (E + 255) / 256;
    int wblk = (int)(((long)N * 32 + 255) / 256);   // warp-per-node grid

    // ---- prep: edge decode, degrees, CSR build ----
    detect_kernel<<<1, 32>>>((const int*)ei);
    zero_cnt_kernel<<<nblk, 256>>>(N);
    prep_edges_kernel<<<eblk, 256>>>(ei, E);
    dis_kernel<<<nblk, 256>>>(N);
    scan1_kernel<<<nblk, 256>>>(N);
    scan2_kernel<<<1, 256>>>(nblk);
    scan3_kernel<<<nblk, 256>>>(N);
    fill_kernel<<<eblk, 256>>>(E);

    // ---- one-time conversions ----
    int wtot = K1 * HD + 6 * HD * HD;
    prep_weights_kernel<<<(wtot + 255) / 256, 256>>>(enc_w1, enc_w2,
        conv_w[0], conv_w[1], conv_w[2], cls_w1, K1);
    int pairs = N * K1 / 2;
    cvt_nf_kernel<<<(pairs + 255) / 256, 256>>>(nf, pairs);

    // ---- node encoder: x = relu(nf@w1+b1) @ w2 + b2 ----
    gemm(pfb0, pwt + WO_ENC1, enc_b1, pb1, N, K1, true);
    gemm(pb1,  pwt + WO_ENC2, enc_b2, pb2, N, HD, false);

    // ---- 3 GCN layers: bf16 GEMM then CSR aggregate (bias+self+relu fused) ----
    // buffers: cur -> (gemm) b1 -> (agg) next
    gemm(pb2, pwt + WO_CONV(0), nullptr, pb1, N, HD, false);
    agg_kernel<true ><<<wblk, 256>>>(pb1, conv_b[0], pb3, N);
    gemm(pb3, pwt + WO_CONV(1), nullptr, pb1, N, HD, false);
    agg_kernel<true ><<<wblk, 256>>>(pb1, conv_b[1], pb2, N);
    gemm(pb2, pwt + WO_CONV(2), nullptr, pb1, N, HD, false);
    agg_kernel<false><<<wblk, 256>>>(pb1, conv_b[2], pb3, N);

    // ---- classifier factorization: A = x3@W1_top + b1, B = x3@W1_bot ----
    gemm(pb3, pwt + WO_CLST, cls_b1,  pb1, N, HD, false);
    gemm(pb3, pwt + WO_CLSB, nullptr, pb2, N, HD, false);

    edge_score_kernel<<<1184, 256>>>(pb1, pb2, cls_w2, cls_b2, (float*)d_out, E);
}

// round 9
// speedup vs baseline: 1.3826x; 1.3826x over previous
#include <cuda_runtime.h>
#include <cuda_bf16.h>
#include <cstdint>

// Problem constants (fixed by the dataset)
#define NN 50000
#define EE 1600000
#define HD 128
#define FDMAX 256

// -------- device scratch (no allocations allowed) --------
__device__ __nv_bfloat16 g_fb0[(size_t)NN * FDMAX];  // bf16 node features
__device__ __nv_bfloat16 g_b1[(size_t)NN * HD];      // bf16 feature buffers
__device__ __nv_bfloat16 g_b2[(size_t)NN * HD];
__device__ __nv_bfloat16 g_b3[(size_t)NN * HD];
__device__ __nv_bfloat16 g_wt[FDMAX * HD + 6 * HD * HD];  // transposed bf16 weights
__device__ float g_dis[NN];
__device__ int   g_cnt[NN];       // in-degree (no self loop)
__device__ int   g_rowstart[NN];  // CSR row start (by dst)
__device__ int   g_woff[NN];      // running write offsets for fill
__device__ int   g_bsum[256];     // block sums for scan
__device__ int   g_boff[256];     // exclusive block offsets
__device__ int2  g_sd[EE];        // (src, dst) per original edge
__device__ int2  g_epack[EE];     // CSR payload: (src, coef bits)
__device__ int   g_is64;

// weight offsets inside g_wt (bf16 elements)
#define WO_ENC1 0                       // [HD][K1]
#define WO_ENC2 (FDMAX * HD)            // [HD][HD]
#define WO_CONV(l) (WO_ENC2 + (1 + (l)) * HD * HD)
#define WO_CLST (WO_ENC2 + 4 * HD * HD)
#define WO_CLSB (WO_ENC2 + 5 * HD * HD)

// ---------------------------------------------------------
// prep: detect edge dtype (int64 vs int32)
// ---------------------------------------------------------
__global__ void detect_kernel(const int* __restrict__ ei32) {
    if (blockIdx.x == 0 && threadIdx.x == 0) {
        int orv = 0;
        #pragma unroll
        for (int i = 0; i < 16; i++) orv |= ei32[2 * i + 1];
        g_is64 = (orv == 0) ? 1 : 0;   // int64 high words are 0 (values < 50000)
    }
}

__global__ void zero_cnt_kernel(int n) {
    int i = blockIdx.x * blockDim.x + threadIdx.x;
    if (i < n) g_cnt[i] = 0;
}

__global__ void prep_edges_kernel(const void* __restrict__ eiv, int E) {
    int e = blockIdx.x * blockDim.x + threadIdx.x;
    if (e >= E) return;
    int s, d;
    if (g_is64) {
        const long long* ei = (const long long*)eiv;
        s = (int)ei[e];
        d = (int)ei[(size_t)E + e];
    } else {
        const int* ei = (const int*)eiv;
        s = ei[e];
        d = ei[E + e];
    }
    g_sd[e] = make_int2(s, d);
    atomicAdd(&g_cnt[d], 1);
}

__global__ void dis_kernel(int n) {
    int i = blockIdx.x * blockDim.x + threadIdx.x;
    if (i < n) g_dis[i] = rsqrtf((float)g_cnt[i] + 1.0f);  // +1 self-loop
}

// -------- 2-level exclusive scan of g_cnt -> g_rowstart, g_woff --------
__global__ void scan1_kernel(int n) {
    __shared__ int sh[256];
    int tx = threadIdx.x;
    int i  = blockIdx.x * 256 + tx;
    int v  = (i < n) ? g_cnt[i] : 0;
    sh[tx] = v;
    __syncthreads();
    #pragma unroll
    for (int o = 1; o < 256; o <<= 1) {
        int t = (tx >= o) ? sh[tx - o] : 0;
        __syncthreads();
        sh[tx] += t;
        __syncthreads();
    }
    if (i < n) g_rowstart[i] = sh[tx];
    if (tx == 255) g_bsum[blockIdx.x] = sh[255];
}

__global__ void scan2_kernel(int nb) {
    __shared__ int sh[256];
    int tx = threadIdx.x;
    int v  = (tx < nb) ? g_bsum[tx] : 0;
    sh[tx] = v;
    __syncthreads();
    #pragma unroll
    for (int o = 1; o < 256; o <<= 1) {
        int t = (tx >= o) ? sh[tx - o] : 0;
        __syncthreads();
        sh[tx] += t;
        __syncthreads();
    }
    if (tx < nb) g_boff[tx] = sh[tx] - v;
}

__global__ void scan3_kernel(int n) {
    int i = blockIdx.x * blockDim.x + threadIdx.x;
    if (i < n) {
        int start = g_rowstart[i] + g_boff[blockIdx.x] - g_cnt[i];
        g_rowstart[i] = start;
        g_woff[i]     = start;
    }
}

__global__ void fill_kernel(int E) {
    int e = blockIdx.x * blockDim.x + threadIdx.x;
    if (e >= E) return;
    int2 sd = g_sd[e];
    int pos = atomicAdd(&g_woff[sd.y], 1);
    float coef = g_dis[sd.x] * g_dis[sd.y];
    g_epack[pos] = make_int2(sd.x, __float_as_int(coef));
}

// ---------------------------------------------------------
// one-time conversions: weights -> transposed bf16 [n][k], node feats -> bf16
// ---------------------------------------------------------
__global__ void prep_weights_kernel(const float* __restrict__ ew1,
                                    const float* __restrict__ ew2,
                                    const float* __restrict__ cw1,
                                    const float* __restrict__ cw2,
                                    const float* __restrict__ cw3,
                                    const float* __restrict__ clw1, int K1)
{
    int idx = blockIdx.x * blockDim.x + threadIdx.x;
    int enc1_sz = K1 * HD;
    if (idx < enc1_sz) {
        int n = idx / K1, k = idx % K1;
        g_wt[WO_ENC1 + idx] = __float2bfloat16(ew1[k * HD + n]);
        return;
    }
    int r = idx - enc1_sz;
    int seg = r / (HD * HD);
    if (seg >= 6) return;
    int rr = r % (HD * HD);
    int n = rr / HD, k = rr % HD;
    const float* w;
    switch (seg) {
        case 0: w = ew2; break;
        case 1: w = cw1; break;
        case 2: w = cw2; break;
        case 3: w = cw3; break;
        case 4: w = clw1; break;
        default: w = clw1 + HD * HD; break;
    }
    g_wt[enc1_sz + seg * HD * HD + n * HD + k] = __float2bfloat16(w[k * HD + n]);
}

__global__ void cvt_nf_kernel(const float* __restrict__ nf, int total_pairs) {
    int i = blockIdx.x * blockDim.x + threadIdx.x;
    if (i < total_pairs) {
        float2 v = ((const float2*)nf)[i];
        ((__nv_bfloat162*)g_fb0)[i] = __floats2bfloat162_rn(v.x, v.y);
    }
}

// ---------------------------------------------------------
// BF16 tensor-core GEMM: C[M,128] = A[M,K](bf16) @ Wt[128,K]^T + bias [,relu]
// BM=128, BN=128, BK=32, 256 threads (8 warps, 4x2), warp tile 32x64
// Fragments via ldmatrix.x4 (conflict-free with TS=40 row stride).
// ---------------------------------------------------------
__device__ __forceinline__ void mma_bf16(float c[4],
                                         uint32_t a0, uint32_t a1, uint32_t a2, uint32_t a3,
                                         uint32_t b0, uint32_t b1) {
    asm volatile(
        "mma.sync.aligned.m16n8k16.row.col.f32.bf16.bf16.f32 "
        "{%0,%1,%2,%3}, {%4,%5,%6,%7}, {%8,%9}, {%0,%1,%2,%3};"
        : "+f"(c[0]), "+f"(c[1]), "+f"(c[2]), "+f"(c[3])
        : "r"(a0), "r"(a1), "r"(a2), "r"(a3), "r"(b0), "r"(b1));
}

#define LDSM4(r0, r1, r2, r3, addr)                                            \
    asm volatile("ldmatrix.sync.aligned.m8n8.x4.shared.b16 {%0,%1,%2,%3}, [%4];" \
                 : "=r"(r0), "=r"(r1), "=r"(r2), "=r"(r3) : "r"(addr))

#define TS 40   // smem row stride in bf16 (32 + 8 pad); 80B -> rows 20 banks apart

template <bool RELU_OUT>
__global__ __launch_bounds__(256, 2) void bgemm_kernel(
    const __nv_bfloat16* __restrict__ A, const __nv_bfloat16* __restrict__ Bt,
    const float* __restrict__ bias, __nv_bfloat16* __restrict__ C, int M, int K)
{
    __shared__ __align__(16) __nv_bfloat16 As[128 * TS];  // [m][k]
    __shared__ __align__(16) __nv_bfloat16 Bs[128 * TS];  // [n][k]

    const int tid    = threadIdx.x;
    const int wid    = tid >> 5;
    const int lane   = tid & 31;
    const int warp_m = wid >> 1;
    const int warp_n = wid & 1;
    const int m0     = blockIdx.x * 128;

    // ldmatrix per-lane addressing
    const int xrow   = lane & 7;
    const int rhalfA = (lane >> 3) & 1;   // A: matrices 1,3 -> +8 rows
    const int kchA   = (lane >> 4) & 1;   // A: matrices 2,3 -> +8 k
    const int rhalfB = (lane >> 4) & 1;   // B: matrices 2,3 -> +8 rows
    const int kchB   = (lane >> 3) & 1;   // B: matrices 1,3 -> +8 k

    uint32_t as_base = (uint32_t)__cvta_generic_to_shared(As);
    uint32_t bs_base = (uint32_t)__cvta_generic_to_shared(Bs);

    // byte addresses (bf16 = 2B)
    uint32_t a_addr[2];
    #pragma unroll
    for (int mt = 0; mt < 2; mt++) {
        int row = warp_m * 32 + mt * 16 + xrow + rhalfA * 8;
        a_addr[mt] = as_base + (row * TS + kchA * 8) * 2;
    }
    uint32_t b_addr[4];
    #pragma unroll
    for (int p = 0; p < 4; p++) {
        int row = warp_n * 64 + p * 16 + xrow + rhalfB * 8;
        b_addr[p] = bs_base + (row * TS + kchB * 8) * 2;
    }

    float acc[2][8][4];
    #pragma unroll
    for (int mt = 0; mt < 2; mt++)
        #pragma unroll
        for (int nt = 0; nt < 8; nt++)
            #pragma unroll
            for (int i = 0; i < 4; i++) acc[mt][nt][i] = 0.0f;

    for (int k0 = 0; k0 < K; k0 += 32) {
        // A tile: 128 rows x 32 k bf16 (64B/row) -> 512 uint4, 2 per thread
        #pragma unroll
        for (int i = 0; i < 2; i++) {
            int fi  = tid + i * 256;
            int row = fi >> 2, c = fi & 3;
            uint4 v = make_uint4(0u, 0u, 0u, 0u);
            if (m0 + row < M)
                v = __ldg((const uint4*)(A + (size_t)(m0 + row) * K + k0) + c);
            *(uint4*)&As[row * TS + c * 8] = v;
        }
        // B tile: 128 n-rows x 32 k bf16 from transposed weights
        #pragma unroll
        for (int i = 0; i < 2; i++) {
            int fi = tid + i * 256;
            int n  = fi >> 2, c = fi & 3;
            uint4 v = __ldg((const uint4*)(Bt + (size_t)n * K + k0) + c);
            *(uint4*)&Bs[n * TS + c * 8] = v;
        }
        __syncthreads();

        #pragma unroll
        for (int kk = 0; kk < 2; kk++) {     // kk*16 within BK=32
            uint32_t af[2][4];
            #pragma unroll
            for (int mt = 0; mt < 2; mt++)
                LDSM4(af[mt][0], af[mt][1], af[mt][2], af[mt][3],
                      a_addr[mt] + kk * 32);
            uint32_t bfr[8][2];
            #pragma unroll
            for (int p = 0; p < 4; p++)
                LDSM4(bfr[2 * p][0], bfr[2 * p][1], bfr[2 * p + 1][0], bfr[2 * p + 1][1],
                      b_addr[p] + kk * 32);
            #pragma unroll
            for (int mt = 0; mt < 2; mt++)
                #pragma unroll
                for (int nt = 0; nt < 8; nt++)
                    mma_bf16(acc[mt][nt], af[mt][0], af[mt][1], af[mt][2], af[mt][3],
                             bfr[nt][0], bfr[nt][1]);
        }
        __syncthreads();
    }

    // epilogue: bias + optional relu, bf16x2 stores
    const int gid = lane >> 2;
    const int tig = lane & 3;
    #pragma unroll
    for (int mt = 0; mt < 2; mt++) {
        #pragma unroll
        for (int half = 0; half < 2; half++) {
            int m = m0 + warp_m * 32 + mt * 16 + gid + half * 8;
            if (m < M) {
                #pragma unroll
                for (int nt = 0; nt < 8; nt++) {
                    int col = warp_n * 64 + nt * 8 + tig * 2;
                    float v0 = acc[mt][nt][half * 2 + 0];
                    float v1 = acc[mt][nt][half * 2 + 1];
                    if (bias) {
                        v0 += __ldg(&bias[col]);
                        v1 += __ldg(&bias[col + 1]);
                    }
                    if (RELU_OUT) { v0 = fmaxf(v0, 0.f); v1 = fmaxf(v1, 0.f); }
                    *(__nv_bfloat162*)(C + (size_t)m * HD + col) =
                        __floats2bfloat162_rn(v0, v1);
                }
            }
        }
    }
}

// ---------------------------------------------------------
// load 4 bf16 features (8B) for (row, lane): features lane*4 .. lane*4+3
// ---------------------------------------------------------
__device__ __forceinline__ float4 ld_bf4(const __nv_bfloat16* __restrict__ base,
                                         int row, int lane) {
    uint2 u = __ldg((const uint2*)(base + (size_t)row * HD) + lane);
    __nv_bfloat162 p0 = *reinterpret_cast<__nv_bfloat162*>(&u.x);
    __nv_bfloat162 p1 = *reinterpret_cast<__nv_bfloat162*>(&u.y);
    float2 f0 = __bfloat1622float2(p0);
    float2 f1 = __bfloat1622float2(p1);
    return make_float4(f0.x, f0.y, f1.x, f1.y);
}

// ---------------------------------------------------------
// CSR aggregation (R6-proven form): one warp per dst node, 4-deep unroll,
// fp32 accumulate, bf16 output.
// out[i] = [relu]( bias + dis[i]^2 * xw[i] + sum_j coef_j * xw[src_j] )
// ---------------------------------------------------------
template <bool RELU>
__global__ void agg_kernel(const __nv_bfloat16* __restrict__ xw,
                           const float* __restrict__ bias,
                           __nv_bfloat16* __restrict__ out, int n)
{
    int g    = blockIdx.x * blockDim.x + threadIdx.x;
    int node = g >> 5;
    int lane = g & 31;
    if (node >= n) return;

    int start = g_rowstart[node];
    int deg   = g_cnt[node];
    float ds  = g_dis[node];
    float c   = ds * ds;

    float4 b = ((const float4*)bias)[lane];
    float4 v = ld_bf4(xw, node, lane);
    float4 acc = make_float4(fmaf(v.x, c, b.x), fmaf(v.y, c, b.y),
                             fmaf(v.z, c, b.z), fmaf(v.w, c, b.w));

    const int2* ep = g_epack + start;
    int j = 0;
    for (; j + 4 <= deg; j += 4) {
        int2 e0 = __ldg(ep + j);
        int2 e1 = __ldg(ep + j + 1);
        int2 e2 = __ldg(ep + j + 2);
        int2 e3 = __ldg(ep + j + 3);
        float4 u0 = ld_bf4(xw, e0.x, lane);
        float4 u1 = ld_bf4(xw, e1.x, lane);
        float4 u2 = ld_bf4(xw, e2.x, lane);
        float4 u3 = ld_bf4(xw, e3.x, lane);
        float w0 = __int_as_float(e0.y), w1 = __int_as_float(e1.y);
        float w2 = __int_as_float(e2.y), w3 = __int_as_float(e3.y);
        acc.x = fmaf(u0.x, w0, acc.x); acc.y = fmaf(u0.y, w0, acc.y);
        acc.z = fmaf(u0.z, w0, acc.z); acc.w = fmaf(u0.w, w0, acc.w);
        acc.x = fmaf(u1.x, w1, acc.x); acc.y = fmaf(u1.y, w1, acc.y);
        acc.z = fmaf(u1.z, w1, acc.z); acc.w = fmaf(u1.w, w1, acc.w);
        acc.x = fmaf(u2.x, w2, acc.x); acc.y = fmaf(u2.y, w2, acc.y);
        acc.z = fmaf(u2.z, w2, acc.z); acc.w = fmaf(u2.w, w2, acc.w);
        acc.x = fmaf(u3.x, w3, acc.x); acc.y = fmaf(u3.y, w3, acc.y);
        acc.z = fmaf(u3.z, w3, acc.z); acc.w = fmaf(u3.w, w3, acc.w);
    }
    for (; j < deg; j++) {
        int2 e0 = __ldg(ep + j);
        float4 u0 = ld_bf4(xw, e0.x, lane);
        float w0 = __int_as_float(e0.y);
        acc.x = fmaf(u0.x, w0, acc.x); acc.y = fmaf(u0.y, w0, acc.y);
        acc.z = fmaf(u0.z, w0, acc.z); acc.w = fmaf(u0.w, w0, acc.w);
    }

    if (RELU) {
        acc.x = fmaxf(acc.x, 0.f); acc.y = fmaxf(acc.y, 0.f);
        acc.z = fmaxf(acc.z, 0.f); acc.w = fmaxf(acc.w, 0.f);
    }
    __nv_bfloat162 h0 = __floats2bfloat162_rn(acc.x, acc.y);
    __nv_bfloat162 h1 = __floats2bfloat162_rn(acc.z, acc.w);
    uint2 u;
    u.x = *(uint32_t*)&h0; u.y = *(uint32_t*)&h1;
    ((uint2*)(out + (size_t)node * HD))[lane] = u;
}

// ---------------------------------------------------------
// edge score (R6-proven form): sigmoid( relu(A[s]+B[d]) . w2 + b2 )
// one warp per edge, lane handles 4 features.
// ---------------------------------------------------------
__global__ void edge_score_kernel(const __nv_bfloat16* __restrict__ Af,
                                  const __nv_bfloat16* __restrict__ Bf,
                                  const float* __restrict__ w2,
                                  const float* __restrict__ b2,
                                  float* __restrict__ out, int E)
{
    int g    = blockIdx.x * blockDim.x + threadIdx.x;
    int e    = g >> 5;
    int lane = g & 31;
    if (e >= E) return;
    int2 sd = __ldg(&g_sd[e]);
    float4 a = ld_bf4(Af, sd.x, lane);
    float4 b = ld_bf4(Bf, sd.y, lane);
    float4 w = __ldg((const float4*)w2 + lane);
    float sum = fmaxf(a.x + b.x, 0.f) * w.x
              + fmaxf(a.y + b.y, 0.f) * w.y
              + fmaxf(a.z + b.z, 0.f) * w.z
              + fmaxf(a.w + b.w, 0.f) * w.w;
    #pragma unroll
    for (int o = 16; o; o >>= 1) sum += __shfl_xor_sync(0xffffffffu, sum, o);
    if (lane == 0) {
        float z = sum + __ldg(b2);
        out[e] = 1.0f / (1.0f + __expf(-z));
    }
}

// ---------------------------------------------------------
// host side
// ---------------------------------------------------------
static void gemm(const __nv_bfloat16* A, const __nv_bfloat16* Bt, const float* bias,
                 __nv_bfloat16* C, int M, int K, bool relu_out)
{
    dim3 grid((M + 127) / 128);
    if (relu_out) bgemm_kernel<true ><<<grid, 256>>>(A, Bt, bias, C, M, K);
    else          bgemm_kernel<false><<<grid, 256>>>(A, Bt, bias, C, M, K);
}

extern "C" void kernel_launch(void* const* d_in, const int* in_sizes, int n_in,
                              void* d_out, int out_size)
{
    const float* nf      = (const float*)d_in[0];
    const void*  ei      = d_in[1];
    const float* enc_w1  = (const float*)d_in[2];
    const float* enc_b1  = (const float*)d_in[3];
    const float* enc_w2  = (const float*)d_in[4];
    const float* enc_b2  = (const float*)d_in[5];
    const float* conv_w[3] = {(const float*)d_in[6], (const float*)d_in[8], (const float*)d_in[10]};
    const float* conv_b[3] = {(const float*)d_in[7], (const float*)d_in[9], (const float*)d_in[11]};
    const float* cls_w1  = (const float*)d_in[12];
    const float* cls_b1  = (const float*)d_in[13];
    const float* cls_w2  = (const float*)d_in[14];
    const float* cls_b2  = (const float*)d_in[15];

    int K1 = in_sizes[2] / HD;        // encoder input dim (256)
    int N  = in_sizes[0] / K1;        // nodes
    int E  = in_sizes[1] / 2;         // edges

    __nv_bfloat16 *pfb0, *pb1, *pb2, *pb3, *pwt;
    cudaGetSymbolAddress((void**)&pfb0, g_fb0);
    cudaGetSymbolAddress((void**)&pb1,  g_b1);
    cudaGetSymbolAddress((void**)&pb2,  g_b2);
    cudaGetSymbolAddress((void**)&pb3,  g_b3);
    cudaGetSymbolAddress((void**)&pwt,  g_wt);

    int nblk  = (N + 255) / 256;
    int eblk  = (E + 255) / 256;
    int wblk  = (int)(((long)N * 32 + 255) / 256);   // warp-per-node grid
    int ewblk = (int)(((long)E * 32 + 255) / 256);   // warp-per-edge grid

    // ---- prep: edge decode, degrees, CSR build ----
    detect_kernel<<<1, 32>>>((const int*)ei);
    zero_cnt_kernel<<<nblk, 256>>>(N);
    prep_edges_kernel<<<eblk, 256>>>(ei, E);
    dis_kernel<<<nblk, 256>>>(N);
    scan1_kernel<<<nblk, 256>>>(N);
    scan2_kernel<<<1, 256>>>(nblk);
    scan3_kernel<<<nblk, 256>>>(N);
    fill_kernel<<<eblk, 256>>>(E);

    // ---- one-time conversions ----
    int wtot = K1 * HD + 6 * HD * HD;
    prep_weights_kernel<<<(wtot + 255) / 256, 256>>>(enc_w1, enc_w2,
        conv_w[0], conv_w[1], conv_w[2], cls_w1, K1);
    int pairs = N * K1 / 2;
    cvt_nf_kernel<<<(pairs + 255) / 256, 256>>>(nf, pairs);

    // ---- node encoder: x = relu(nf@w1+b1) @ w2 + b2 ----
    gemm(pfb0, pwt + WO_ENC1, enc_b1, pb1, N, K1, true);
    gemm(pb1,  pwt + WO_ENC2, enc_b2, pb2, N, HD, false);

    // ---- 3 GCN layers: bf16 GEMM then CSR aggregate (bias+self+relu fused) ----
    gemm(pb2, pwt + WO_CONV(0), nullptr, pb1, N, HD, false);
    agg_kernel<true ><<<wblk, 256>>>(pb1, conv_b[0], pb3, N);
    gemm(pb3, pwt + WO_CONV(1), nullptr, pb1, N, HD, false);
    agg_kernel<true ><<<wblk, 256>>>(pb1, conv_b[1], pb2, N);
    gemm(pb2, pwt + WO_CONV(2), nullptr, pb1, N, HD, false);
    agg_kernel<false><<<wblk, 256>>>(pb1, conv_b[2], pb3, N);

    // ---- classifier factorization: A = x3@W1_top + b1, B = x3@W1_bot ----
    gemm(pb3, pwt + WO_CLST, cls_b1,  pb1, N, HD, false);
    gemm(pb3, pwt + WO_CLSB, nullptr, pb2, N, HD, false);

    edge_score_kernel<<<ewblk, 256>>>(pb1, pb2, cls_w2, cls_b2, (float*)d_out, E);
}

// round 10
// speedup vs baseline: 1.7574x; 1.2711x over previous
#include <cuda_runtime.h>
#include <cuda_bf16.h>
#include <cstdint>

// Problem constants (fixed by the dataset)
#define NN 50000
#define EE 1600000
#define HD 128
#define FDMAX 256

// -------- device scratch (no allocations allowed) --------
__device__ __nv_bfloat16 g_fb0[(size_t)NN * FDMAX];  // bf16 node feats / classifier [A|B]
__device__ __nv_bfloat16 g_b1[(size_t)NN * HD];      // bf16 feature buffers
__device__ __nv_bfloat16 g_b2[(size_t)NN * HD];
__device__ __nv_bfloat16 g_b3[(size_t)NN * HD];
__device__ __nv_bfloat16 g_wt[FDMAX * HD + 6 * HD * HD];  // transposed bf16 weights
__device__ float g_clsb[2 * HD];  // combined classifier bias [cls_b1 ; 0]
__device__ float g_dis[NN];
__device__ int   g_cnt[NN];       // in-degree (no self loop)
__device__ int   g_rowstart[NN];  // CSR row start (by dst)
__device__ int   g_woff[NN];      // running write offsets for fill
__device__ int   g_bsum[256];     // block sums for scan
__device__ int   g_boff[256];     // exclusive block offsets
__device__ int2  g_sd[EE];        // (src, dst) per original edge
__device__ int2  g_epack[EE];     // CSR payload: (src, coef bits)
__device__ int   g_eorig[EE];     // CSR payload: original edge index
__device__ int   g_is64;

// weight offsets inside g_wt (bf16 elements)
#define WO_ENC1 0                       // [HD][K1]
#define WO_ENC2 (FDMAX * HD)            // [HD][HD]
#define WO_CONV(l) (WO_ENC2 + (1 + (l)) * HD * HD)
#define WO_CLS (WO_ENC2 + 4 * HD * HD)  // [256][HD]  (A rows 0..127, B rows 128..255)

// ---------------------------------------------------------
// prep: detect edge dtype (int64 vs int32)
// ---------------------------------------------------------
__global__ void detect_kernel(const int* __restrict__ ei32) {
    if (blockIdx.x == 0 && threadIdx.x == 0) {
        int orv = 0;
        #pragma unroll
        for (int i = 0; i < 16; i++) orv |= ei32[2 * i + 1];
        g_is64 = (orv == 0) ? 1 : 0;   // int64 high words are 0 (values < 50000)
    }
}

__global__ void zero_cnt_kernel(int n) {
    int i = blockIdx.x * blockDim.x + threadIdx.x;
    if (i < n) g_cnt[i] = 0;
}

__global__ void prep_edges_kernel(const void* __restrict__ eiv, int E) {
    int e = blockIdx.x * blockDim.x + threadIdx.x;
    if (e >= E) return;
    int s, d;
    if (g_is64) {
        const long long* ei = (const long long*)eiv;
        s = (int)ei[e];
        d = (int)ei[(size_t)E + e];
    } else {
        const int* ei = (const int*)eiv;
        s = ei[e];
        d = ei[E + e];
    }
    g_sd[e] = make_int2(s, d);
    atomicAdd(&g_cnt[d], 1);
}

__global__ void dis_kernel(int n) {
    int i = blockIdx.x * blockDim.x + threadIdx.x;
    if (i < n) g_dis[i] = rsqrtf((float)g_cnt[i] + 1.0f);  // +1 self-loop
}

// -------- 2-level exclusive scan of g_cnt -> g_rowstart, g_woff --------
__global__ void scan1_kernel(int n) {
    __shared__ int sh[256];
    int tx = threadIdx.x;
    int i  = blockIdx.x * 256 + tx;
    int v  = (i < n) ? g_cnt[i] : 0;
    sh[tx] = v;
    __syncthreads();
    #pragma unroll
    for (int o = 1; o < 256; o <<= 1) {
        int t = (tx >= o) ? sh[tx - o] : 0;
        __syncthreads();
        sh[tx] += t;
        __syncthreads();
    }
    if (i < n) g_rowstart[i] = sh[tx];
    if (tx == 255) g_bsum[blockIdx.x] = sh[255];
}

__global__ void scan2_kernel(int nb) {
    __shared__ int sh[256];
    int tx = threadIdx.x;
    int v  = (tx < nb) ? g_bsum[tx] : 0;
    sh[tx] = v;
    __syncthreads();
    #pragma unroll
    for (int o = 1; o < 256; o <<= 1) {
        int t = (tx >= o) ? sh[tx - o] : 0;
        __syncthreads();
        sh[tx] += t;
        __syncthreads();
    }
    if (tx < nb) g_boff[tx] = sh[tx] - v;
}

__global__ void scan3_kernel(int n) {
    int i = blockIdx.x * blockDim.x + threadIdx.x;
    if (i < n) {
        int start = g_rowstart[i] + g_boff[blockIdx.x] - g_cnt[i];
        g_rowstart[i] = start;
        g_woff[i]     = start;
    }
}

__global__ void fill_kernel(int E) {
    int e = blockIdx.x * blockDim.x + threadIdx.x;
    if (e >= E) return;
    int2 sd = g_sd[e];
    int pos = atomicAdd(&g_woff[sd.y], 1);
    float coef = g_dis[sd.x] * g_dis[sd.y];
    g_epack[pos] = make_int2(sd.x, __float_as_int(coef));
    g_eorig[pos] = e;
}

// ---------------------------------------------------------
// one-time conversions: weights -> transposed bf16 [n][k], node feats -> bf16
// ---------------------------------------------------------
__global__ void prep_weights_kernel(const float* __restrict__ ew1,
                                    const float* __restrict__ ew2,
                                    const float* __restrict__ cw1,
                                    const float* __restrict__ cw2,
                                    const float* __restrict__ cw3,
                                    const float* __restrict__ clw1,
                                    const float* __restrict__ clb1, int K1)
{
    int idx = blockIdx.x * blockDim.x + threadIdx.x;
    if (idx < 2 * HD)   // combined classifier bias
        g_clsb[idx] = (idx < HD) ? clb1[idx] : 0.0f;
    int enc1_sz = K1 * HD;
    if (idx < enc1_sz) {
        int n = idx / K1, k = idx % K1;
        g_wt[WO_ENC1 + idx] = __float2bfloat16(ew1[k * HD + n]);
        return;
    }
    int r = idx - enc1_sz;
    int seg = r / (HD * HD);
    if (seg >= 6) return;
    int rr = r % (HD * HD);
    int n = rr / HD, k = rr % HD;
    const float* w;
    switch (seg) {
        case 0: w = ew2; break;
        case 1: w = cw1; break;
        case 2: w = cw2; break;
        case 3: w = cw3; break;
        case 4: w = clw1; break;             // classifier A-half (rows 0..127 of cls_w1)
        default: w = clw1 + HD * HD; break;  // classifier B-half
    }
    g_wt[enc1_sz + seg * HD * HD + n * HD + k] = __float2bfloat16(w[k * HD + n]);
}

__global__ void cvt_nf_kernel(const float* __restrict__ nf, int total_pairs) {
    int i = blockIdx.x * blockDim.x + threadIdx.x;
    if (i < total_pairs) {
        float2 v = ((const float2*)nf)[i];
        ((__nv_bfloat162*)g_fb0)[i] = __floats2bfloat162_rn(v.x, v.y);
    }
}

// ---------------------------------------------------------
// BF16 tensor-core GEMM with cp.async double buffering.
// C[M, OS-wide] block (blockIdx.y selects 128-col n-block)
//   = A[M,K](bf16) @ Wt[NB*128,K]^T + bias [,relu]
// BM=128, BN=128, BK=32, 256 threads (8 warps, 4x2), ldmatrix fragments.
// ---------------------------------------------------------
__device__ __forceinline__ void mma_bf16(float c[4],
                                         uint32_t a0, uint32_t a1, uint32_t a2, uint32_t a3,
                                         uint32_t b0, uint32_t b1) {
    asm volatile(
        "mma.sync.aligned.m16n8k16.row.col.f32.bf16.bf16.f32 "
        "{%0,%1,%2,%3}, {%4,%5,%6,%7}, {%8,%9}, {%0,%1,%2,%3};"
        : "+f"(c[0]), "+f"(c[1]), "+f"(c[2]), "+f"(c[3])
        : "r"(a0), "r"(a1), "r"(a2), "r"(a3), "r"(b0), "r"(b1));
}

#define LDSM4(r0, r1, r2, r3, addr)                                            \
    asm volatile("ldmatrix.sync.aligned.m8n8.x4.shared.b16 {%0,%1,%2,%3}, [%4];" \
                 : "=r"(r0), "=r"(r1), "=r"(r2), "=r"(r3) : "r"(addr))

#define CP_ASYNC16(saddr, gptr, sz)                                            \
    asm volatile("cp.async.cg.shared.global [%0], [%1], 16, %2;"               \
                 :: "r"(saddr), "l"(gptr), "r"(sz))
#define CP_COMMIT() asm volatile("cp.async.commit_group;")

#define TS 40   // smem row stride in bf16 (32 + 8 pad); 80B -> rows 20 banks apart
#define TILE_ELEMS (128 * TS)            // elements per tile buffer
#define TILE_BYTES (TILE_ELEMS * 2)      // 10240 B

template <bool RELU_OUT>
__global__ __launch_bounds__(256, 2) void bgemm_kernel(
    const __nv_bfloat16* __restrict__ A, const __nv_bfloat16* __restrict__ Bt,
    const float* __restrict__ bias, __nv_bfloat16* __restrict__ C,
    int M, int K, int OS)
{
    // layout: A buf0 | A buf1 | B buf0 | B buf1
    __shared__ __align__(16) __nv_bfloat16 smem[4 * TILE_ELEMS];

    const int tid    = threadIdx.x;
    const int wid    = tid >> 5;
    const int lane   = tid & 31;
    const int warp_m = wid >> 1;
    const int warp_n = wid & 1;
    const int m0     = blockIdx.x * 128;
    const int n0     = blockIdx.y * 128;

    uint32_t s_base = (uint32_t)__cvta_generic_to_shared(smem);

    // ldmatrix per-lane addressing (relative to buffer base)
    const int xrow   = lane & 7;
    const int rhalfA = (lane >> 3) & 1;
    const int kchA   = (lane >> 4) & 1;
    const int rhalfB = (lane >> 4) & 1;
    const int kchB   = (lane >> 3) & 1;

    uint32_t a_off[2];
    #pragma unroll
    for (int mt = 0; mt < 2; mt++) {
        int row = warp_m * 32 + mt * 16 + xrow + rhalfA * 8;
        a_off[mt] = (uint32_t)((row * TS + kchA * 8) * 2);
    }
    uint32_t b_off[4];
    #pragma unroll
    for (int p = 0; p < 4; p++) {
        int row = warp_n * 64 + p * 16 + xrow + rhalfB * 8;
        b_off[p] = (uint32_t)((row * TS + kchB * 8) * 2);
    }

    // cp.async load of one 32-wide k-tile into buffer `buf`
    const int l_row = tid >> 2;          // 0..63 (+64 with second step)
    const int l_c   = tid & 3;           // 16B chunk within 64B row-slice
    auto load_tile = [&](int k0, int buf) {
        #pragma unroll
        for (int i = 0; i < 2; i++) {
            int row = l_row + i * 64;
            // A
            int ga   = m0 + row;
            int szA  = (ga < M) ? 16 : 0;
            int gac  = (ga < M) ? ga : (M - 1);
            uint32_t sa = s_base + buf * TILE_BYTES + (uint32_t)((row * TS + l_c * 8) * 2);
            CP_ASYNC16(sa, A + (size_t)gac * K + k0 + l_c * 8, szA);
            // B
            uint32_t sb = s_base + (2 + buf) * TILE_BYTES + (uint32_t)((row * TS + l_c * 8) * 2);
            CP_ASYNC16(sb, Bt + (size_t)(n0 + row) * K + k0 + l_c * 8, 16);
        }
    };

    float acc[2][8][4];
    #pragma unroll
    for (int mt = 0; mt < 2; mt++)
        #pragma unroll
        for (int nt = 0; nt < 8; nt++)
            #pragma unroll
            for (int i = 0; i < 4; i++) acc[mt][nt][i] = 0.0f;

    const int nk = K >> 5;
    load_tile(0, 0);
    CP_COMMIT();

    for (int it = 0; it < nk; it++) {
        int buf = it & 1;
        if (it + 1 < nk) {
            load_tile((it + 1) << 5, (it + 1) & 1);
            CP_COMMIT();
            asm volatile("cp.async.wait_group 1;");
        } else {
            asm volatile("cp.async.wait_group 0;");
        }
        __syncthreads();

        uint32_t abase = s_base + buf * TILE_BYTES;
        uint32_t bbase = s_base + (2 + buf) * TILE_BYTES;
        #pragma unroll
        for (int kk = 0; kk < 2; kk++) {
            uint32_t af[2][4];
            #pragma unroll
            for (int mt = 0; mt < 2; mt++)
                LDSM4(af[mt][0], af[mt][1], af[mt][2], af[mt][3],
                      abase + a_off[mt] + kk * 32);
            uint32_t bfr[8][2];
            #pragma unroll
            for (int p = 0; p < 4; p++)
                LDSM4(bfr[2 * p][0], bfr[2 * p][1], bfr[2 * p + 1][0], bfr[2 * p + 1][1],
                      bbase + b_off[p] + kk * 32);
            #pragma unroll
            for (int mt = 0; mt < 2; mt++)
                #pragma unroll
                for (int nt = 0; nt < 8; nt++)
                    mma_bf16(acc[mt][nt], af[mt][0], af[mt][1], af[mt][2], af[mt][3],
                             bfr[nt][0], bfr[nt][1]);
        }
        __syncthreads();
    }

    // epilogue: bias + optional relu, bf16x2 stores
    const int gid = lane >> 2;
    const int tig = lane & 3;
    #pragma unroll
    for (int mt = 0; mt < 2; mt++) {
        #pragma unroll
        for (int half = 0; half < 2; half++) {
            int m = m0 + warp_m * 32 + mt * 16 + gid + half * 8;
            if (m < M) {
                #pragma unroll
                for (int nt = 0; nt < 8; nt++) {
                    int col = warp_n * 64 + nt * 8 + tig * 2;
                    float v0 = acc[mt][nt][half * 2 + 0];
                    float v1 = acc[mt][nt][half * 2 + 1];
                    if (bias) {
                        v0 += __ldg(&bias[n0 + col]);
                        v1 += __ldg(&bias[n0 + col + 1]);
                    }
                    if (RELU_OUT) { v0 = fmaxf(v0, 0.f); v1 = fmaxf(v1, 0.f); }
                    *(__nv_bfloat162*)(C + (size_t)m * OS + n0 + col) =
                        __floats2bfloat162_rn(v0, v1);
                }
            }
        }
    }
}

// ---------------------------------------------------------
// helpers
// ---------------------------------------------------------
__device__ __forceinline__ float4 ld_bf4(const __nv_bfloat16* __restrict__ base,
                                         int row, int lane) {
    uint2 u = __ldg((const uint2*)(base + (size_t)row * HD) + lane);
    __nv_bfloat162 p0 = *reinterpret_cast<__nv_bfloat162*>(&u.x);
    __nv_bfloat162 p1 = *reinterpret_cast<__nv_bfloat162*>(&u.y);
    float2 f0 = __bfloat1622float2(p0);
    float2 f1 = __bfloat1622float2(p1);
    return make_float4(f0.x, f0.y, f1.x, f1.y);
}

__device__ __forceinline__ void bf8_to_f(uint4 u, float* f) {
    __nv_bfloat162* p = (__nv_bfloat162*)&u;
    float2 a = __bfloat1622float2(p[0]);
    float2 b = __bfloat1622float2(p[1]);
    float2 c = __bfloat1622float2(p[2]);
    float2 d = __bfloat1622float2(p[3]);
    f[0] = a.x; f[1] = a.y; f[2] = b.x; f[3] = b.y;
    f[4] = c.x; f[5] = c.y; f[6] = d.x; f[7] = d.y;
}

// ---------------------------------------------------------
// CSR aggregation: one warp per dst node, 4-deep unroll,
// fp32 accumulate, bf16 output.
// out[i] = [relu]( bias + dis[i]^2 * xw[i] + sum_j coef_j * xw[src_j] )
// ---------------------------------------------------------
template <bool RELU>
__global__ void agg_kernel(const __nv_bfloat16* __restrict__ xw,
                           const float* __restrict__ bias,
                           __nv_bfloat16* __restrict__ out, int n)
{
    int g    = blockIdx.x * blockDim.x + threadIdx.x;
    int node = g >> 5;
    int lane = g & 31;
    if (node >= n) return;

    int start = g_rowstart[node];
    int deg   = g_cnt[node];
    float ds  = g_dis[node];
    float c   = ds * ds;

    float4 b = ((const float4*)bias)[lane];
    float4 v = ld_bf4(xw, node, lane);
    float4 acc = make_float4(fmaf(v.x, c, b.x), fmaf(v.y, c, b.y),
                             fmaf(v.z, c, b.z), fmaf(v.w, c, b.w));

    const int2* ep = g_epack + start;
    int j = 0;
    for (; j + 4 <= deg; j += 4) {
        int2 e0 = __ldg(ep + j);
        int2 e1 = __ldg(ep + j + 1);
        int2 e2 = __ldg(ep + j + 2);
        int2 e3 = __ldg(ep + j + 3);
        float4 u0 = ld_bf4(xw, e0.x, lane);
        float4 u1 = ld_bf4(xw, e1.x, lane);
        float4 u2 = ld_bf4(xw, e2.x, lane);
        float4 u3 = ld_bf4(xw, e3.x, lane);
        float w0 = __int_as_float(e0.y), w1 = __int_as_float(e1.y);
        float w2 = __int_as_float(e2.y), w3 = __int_as_float(e3.y);
        acc.x = fmaf(u0.x, w0, acc.x); acc.y = fmaf(u0.y, w0, acc.y);
        acc.z = fmaf(u0.z, w0, acc.z); acc.w = fmaf(u0.w, w0, acc.w);
        acc.x = fmaf(u1.x, w1, acc.x); acc.y = fmaf(u1.y, w1, acc.y);
        acc.z = fmaf(u1.z, w1, acc.z); acc.w = fmaf(u1.w, w1, acc.w);
        acc.x = fmaf(u2.x, w2, acc.x); acc.y = fmaf(u2.y, w2, acc.y);
        acc.z = fmaf(u2.z, w2, acc.z); acc.w = fmaf(u2.w, w2, acc.w);
        acc.x = fmaf(u3.x, w3, acc.x); acc.y = fmaf(u3.y, w3, acc.y);
        acc.z = fmaf(u3.z, w3, acc.z); acc.w = fmaf(u3.w, w3, acc.w);
    }
    for (; j < deg; j++) {
        int2 e0 = __ldg(ep + j);
        float4 u0 = ld_bf4(xw, e0.x, lane);
        float w0 = __int_as_float(e0.y);
        acc.x = fmaf(u0.x, w0, acc.x); acc.y = fmaf(u0.y, w0, acc.y);
        acc.z = fmaf(u0.z, w0, acc.z); acc.w = fmaf(u0.w, w0, acc.w);
    }

    if (RELU) {
        acc.x = fmaxf(acc.x, 0.f); acc.y = fmaxf(acc.y, 0.f);
        acc.z = fmaxf(acc.z, 0.f); acc.w = fmaxf(acc.w, 0.f);
    }
    __nv_bfloat162 h0 = __floats2bfloat162_rn(acc.x, acc.y);
    __nv_bfloat162 h1 = __floats2bfloat162_rn(acc.z, acc.w);
    uint2 u;
    u.x = *(uint32_t*)&h0; u.y = *(uint32_t*)&h1;
    ((uint2*)(out + (size_t)node * HD))[lane] = u;
}

// ---------------------------------------------------------
// edge score in CSR (dst-major) order:
//   out[orig_e] = sigmoid( relu(A[src] + B[dst]) . w2 + b2 )
// AB rows are 256-wide: A half at [0,128), B half at [128,256).
// One warp per dst node; B loaded once; two half-warps process 2 edges/iter.
// Each half-warp lane holds 8 features (16B loads); 4-step half-warp reduce.
// ---------------------------------------------------------
__global__ void edge_score_csr_kernel(const __nv_bfloat16* __restrict__ AB,
                                      const float* __restrict__ w2,
                                      const float* __restrict__ b2,
                                      float* __restrict__ out, int n)
{
    int g    = blockIdx.x * blockDim.x + threadIdx.x;
    int node = g >> 5;
    int lane = g & 31;
    if (node >= n) return;
    int hl   = lane & 15;   // feature chunk: feats 8*hl .. 8*hl+7
    int half = lane >> 4;

    int start = g_rowstart[node];
    int deg   = g_cnt[node];

    // B half of this node's row, 8 features per lane
    uint4 ub = __ldg((const uint4*)(AB + (size_t)node * FDMAX + HD) + hl);
    float fb[8]; bf8_to_f(ub, fb);
    float4 w0 = __ldg((const float4*)w2 + hl * 2);
    float4 w1 = __ldg((const float4*)w2 + hl * 2 + 1);
    float bb  = __ldg(b2);

    const int2* ep = g_epack + start;
    const int*  eo = g_eorig + start;

    for (int j = 0; j + 2 <= deg; j += 2) {
        int2 e   = __ldg(ep + j + half);
        int orig = __ldg(eo + j + half);
        uint4 ua = __ldg((const uint4*)(AB + (size_t)e.x * FDMAX) + hl);
        float fa[8]; bf8_to_f(ua, fa);
        float s;
        s  = fmaxf(fa[0] + fb[0], 0.f) * w0.x;
        s += fmaxf(fa[1] + fb[1], 0.f) * w0.y;
        s += fmaxf(fa[2] + fb[2], 0.f) * w0.z;
        s += fmaxf(fa[3] + fb[3], 0.f) * w0.w;
        s += fmaxf(fa[4] + fb[4], 0.f) * w1.x;
        s += fmaxf(fa[5] + fb[5], 0.f) * w1.y;
        s += fmaxf(fa[6] + fb[6], 0.f) * w1.z;
        s += fmaxf(fa[7] + fb[7], 0.f) * w1.w;
        #pragma unroll
        for (int o = 8; o; o >>= 1) s += __shfl_xor_sync(0xffffffffu, s, o);
        if (hl == 0)
            out[orig] = 1.0f / (1.0f + __expf(-(s + bb)));
    }
    if (deg & 1) {
        if (half == 0) {
            int j    = deg - 1;
            int2 e   = __ldg(ep + j);
            int orig = __ldg(eo + j);
            uint4 ua = __ldg((const uint4*)(AB + (size_t)e.x * FDMAX) + hl);
            float fa[8]; bf8_to_f(ua, fa);
            float s;
            s  = fmaxf(fa[0] + fb[0], 0.f) * w0.x;
            s += fmaxf(fa[1] + fb[1], 0.f) * w0.y;
            s += fmaxf(fa[2] + fb[2], 0.f) * w0.z;
            s += fmaxf(fa[3] + fb[3], 0.f) * w0.w;
            s += fmaxf(fa[4] + fb[4], 0.f) * w1.x;
            s += fmaxf(fa[5] + fb[5], 0.f) * w1.y;
            s += fmaxf(fa[6] + fb[6], 0.f) * w1.z;
            s += fmaxf(fa[7] + fb[7], 0.f) * w1.w;
            #pragma unroll
            for (int o = 8; o; o >>= 1) s += __shfl_xor_sync(0x0000ffffu, s, o);
            if (hl == 0)
                out[orig] = 1.0f / (1.0f + __expf(-(s + bb)));
        }
    }
}

// ---------------------------------------------------------
// host side
// ---------------------------------------------------------
static void gemm(const __nv_bfloat16* A, const __nv_bfloat16* Bt, const float* bias,
                 __nv_bfloat16* C, int M, int K, int nb, int OS, bool relu_out)
{
    dim3 grid((M + 127) / 128, nb);
    if (relu_out) bgemm_kernel<true ><<<grid, 256>>>(A, Bt, bias, C, M, K, OS);
    else          bgemm_kernel<false><<<grid, 256>>>(A, Bt, bias, C, M, K, OS);
}

extern "C" void kernel_launch(void* const* d_in, const int* in_sizes, int n_in,
                              void* d_out, int out_size)
{
    const float* nf      = (const float*)d_in[0];
    const void*  ei      = d_in[1];
    const float* enc_w1  = (const float*)d_in[2];
    const float* enc_b1  = (const float*)d_in[3];
    const float* enc_w2  = (const float*)d_in[4];
    const float* enc_b2  = (const float*)d_in[5];
    const float* conv_w[3] = {(const float*)d_in[6], (const float*)d_in[8], (const float*)d_in[10]};
    const float* conv_b[3] = {(const float*)d_in[7], (const float*)d_in[9], (const float*)d_in[11]};
    const float* cls_w1  = (const float*)d_in[12];
    const float* cls_b1  = (const float*)d_in[13];
    const float* cls_w2  = (const float*)d_in[14];
    const float* cls_b2  = (const float*)d_in[15];

    int K1 = in_sizes[2] / HD;        // encoder input dim (256)
    int N  = in_sizes[0] / K1;        // nodes
    int E  = in_sizes[1] / 2;         // edges

    __nv_bfloat16 *pfb0, *pb1, *pb2, *pb3, *pwt;
    float* pclsb;
    cudaGetSymbolAddress((void**)&pfb0,  g_fb0);
    cudaGetSymbolAddress((void**)&pb1,   g_b1);
    cudaGetSymbolAddress((void**)&pb2,   g_b2);
    cudaGetSymbolAddress((void**)&pb3,   g_b3);
    cudaGetSymbolAddress((void**)&pwt,   g_wt);
    cudaGetSymbolAddress((void**)&pclsb, g_clsb);

    int nblk = (N + 255) / 256;
    int eblk = (E + 255) / 256;
    int wblk = (int)(((long)N * 32 + 255) / 256);   // warp-per-node grid

    // ---- prep: edge decode, degrees, CSR build ----
    detect_kernel<<<1, 32>>>((const int*)ei);
    zero_cnt_kernel<<<nblk, 256>>>(N);
    prep_edges_kernel<<<eblk, 256>>>(ei, E);
    dis_kernel<<<nblk, 256>>>(N);
    scan1_kernel<<<nblk, 256>>>(N);
    scan2_kernel<<<1, 256>>>(nblk);
    scan3_kernel<<<nblk, 256>>>(N);
    fill_kernel<<<eblk, 256>>>(E);

    // ---- one-time conversions ----
    int wtot = K1 * HD + 6 * HD * HD;
    prep_weights_kernel<<<(wtot + 255) / 256, 256>>>(enc_w1, enc_w2,
        conv_w[0], conv_w[1], conv_w[2], cls_w1, cls_b1, K1);
    int pairs = N * K1 / 2;
    cvt_nf_kernel<<<(pairs + 255) / 256, 256>>>(nf, pairs);

    // ---- node encoder: x = relu(nf@w1+b1) @ w2 + b2 ----
    gemm(pfb0, pwt + WO_ENC1, enc_b1, pb1, N, K1, 1, HD, true);
    gemm(pb1,  pwt + WO_ENC2, enc_b2, pb2, N, HD, 1, HD, false);

    // ---- 3 GCN layers: bf16 GEMM then CSR aggregate (bias+self+relu fused) ----
    gemm(pb2, pwt + WO_CONV(0), nullptr, pb1, N, HD, 1, HD, false);
    agg_kernel<true ><<<wblk, 256>>>(pb1, conv_b[0], pb3, N);
    gemm(pb3, pwt + WO_CONV(1), nullptr, pb1, N, HD, 1, HD, false);
    agg_kernel<true ><<<wblk, 256>>>(pb1, conv_b[1], pb2, N);
    gemm(pb2, pwt + WO_CONV(2), nullptr, pb1, N, HD, 1, HD, false);
    agg_kernel<false><<<wblk, 256>>>(pb1, conv_b[2], pb3, N);

    // ---- fused classifier GEMM: [A|B] = x3 @ [W1_top ; W1_bot]^T + [b1;0] ----
    gemm(pb3, pwt + WO_CLS, pclsb, pfb0, N, HD, 2, FDMAX, false);

    // ---- edge scores in CSR order, scatter to original edge index ----
    edge_score_csr_kernel<<<wblk, 256>>>(pfb0, cls_w2, cls_b2, (float*)d_out, N);
}